// round 4
// baseline (speedup 1.0000x reference)
#include <cuda_runtime.h>

#define NN 20000
#define NE 300000
#define HD 256

// ---------------- scratch (device globals; referenced ONLY in device code) --
__device__ __align__(16) float g_cnt[NN];
__device__ __align__(16) float g_inv[NN];
__device__ __align__(16) float g_aggr3[NN * 4];
__device__ __align__(16) float g_aggr[NN * HD];
__device__ __align__(16) float g_hA[NN * HD];
__device__ __align__(16) float g_hB[NN * HD];
__device__ __align__(16) float g_z1[(size_t)NE * HD];   // 307 MB intermediate
__device__ int g_row[NE];
__device__ int g_col[NE];
__device__ int g_is64;

// ---------------- small utility kernels ------------------------------------
// zero g_cnt, g_aggr3; init detection flag
__global__ void k_zero_small() {
    int i = blockIdx.x * blockDim.x + threadIdx.x;
    int stride = gridDim.x * blockDim.x;
    if (i == 0) g_is64 = 1;
    for (int j = i; j < NN; j += stride) g_cnt[j] = 0.f;
    for (int j = i; j < NN * 4; j += stride) g_aggr3[j] = 0.f;
}

// Detect edge_index dtype. Safe under both interpretations: reads only the
// first 600000 int32 words. int64 data -> odd words are zero high-words.
__global__ void k_detect(const int* __restrict__ ei32) {
    int i = blockIdx.x * blockDim.x + threadIdx.x;
    int stride = gridDim.x * blockDim.x;
    for (int e = i; e < NE; e += stride) {
        if (ei32[2 * e + 1] != 0) { g_is64 = 0; break; }
    }
}

__global__ void k_zero_aggr() {
    int i = blockIdx.x * blockDim.x + threadIdx.x;
    int stride = gridDim.x * blockDim.x;
    for (int j = i; j < NN * HD / 4; j += stride)
        ((float4*)g_aggr)[j] = make_float4(0.f, 0.f, 0.f, 0.f);
}

__global__ void k_idx_count(const void* __restrict__ eiv) {
    int e = blockIdx.x * blockDim.x + threadIdx.x;
    if (e < NE) {
        int r, c;
        if (g_is64) {
            const long long* ei = (const long long*)eiv;
            r = (int)ei[e];
            c = (int)ei[NE + e];
        } else {
            const int* ei = (const int*)eiv;
            r = ei[e];
            c = ei[NE + e];
        }
        r = min(max(r, 0), NN - 1);
        c = min(max(c, 0), NN - 1);
        g_row[e] = r;
        g_col[e] = c;
        atomicAdd(&g_cnt[c], 1.f);
    }
}

__global__ void k_inv() {
    int n = blockIdx.x * blockDim.x + threadIdx.x;
    if (n < NN) g_inv[n] = 1.f / fmaxf(g_cnt[n], 1.f);
}

__global__ void k_scatter3(const float* __restrict__ x) {
    int e = blockIdx.x * blockDim.x + threadIdx.x;
    if (e < NE) {
        int r = g_row[e], c = g_col[e];
        atomicAdd(&g_aggr3[4 * c + 0], x[3 * r + 0]);
        atomicAdd(&g_aggr3[4 * c + 1], x[3 * r + 1]);
        atomicAdd(&g_aggr3[4 * c + 2], x[3 * r + 2]);
    }
}

// Layer 1: d_in = 3, trivial per-(node, out) kernel. Writes g_hA.
__global__ void k_sage1(const float* __restrict__ x, const float* __restrict__ Wl,
                        const float* __restrict__ bl, const float* __restrict__ Wr) {
    int n = blockIdx.x;
    int j = threadIdx.x;
    __shared__ float a[3], xs[3];
    if (j < 3) {
        a[j]  = g_aggr3[4 * n + j] * g_inv[n];
        xs[j] = x[3 * n + j];
    }
    __syncthreads();
    float v = bl[j];
#pragma unroll
    for (int d = 0; d < 3; d++)
        v += a[d] * Wl[d * HD + j] + xs[d] * Wr[d * HD + j];
    g_hA[n * HD + j] = fmaxf(v, 0.f);
}

// Scatter-add h[row[e]] into g_aggr[col[e]], 4 floats per thread.
// src: 0 -> g_hA, 1 -> g_hB
__global__ void k_scatter(int src) {
    const float* h = src ? g_hB : g_hA;
    int t = blockIdx.x * blockDim.x + threadIdx.x;  // 0 .. NE*64-1
    int e = t >> 6;
    int q = (t & 63) << 2;
    if (e < NE) {
        int r = g_row[e], c = g_col[e];
        float4 v = *(const float4*)(h + r * HD + q);
        float* dst = g_aggr + c * HD + q;
        atomicAdd(dst + 0, v.x);
        atomicAdd(dst + 1, v.y);
        atomicAdd(dst + 2, v.z);
        atomicAdd(dst + 3, v.w);
    }
}

// Fused dual-GEMM SAGE layer: hout = relu( (aggr*inv) @ Wl + hprev @ Wr + bl )
// M=NN, N=HD, virtual K=512 (first 256 -> aggr/Wl, second 256 -> hprev/Wr).
// 64x64 tile, 256 threads, 4x4 per thread, BK=16.
// src: 0 -> read g_hA write g_hB ; 1 -> read g_hB write g_hA
__global__ void k_sage_gemm(int src, const float* __restrict__ Wl,
                            const float* __restrict__ Wr, const float* __restrict__ bl) {
    const float* hprev = src ? g_hB : g_hA;
    float*       hout  = src ? g_hA : g_hB;
    __shared__ float As[16][68];
    __shared__ float Bs[16][68];
    const int tid = threadIdx.x;
    const int m0 = blockIdx.y * 64;
    const int n0 = blockIdx.x * 64;
    const int lm  = tid >> 2;
    const int lk  = (tid & 3) << 2;
    const int lbk = tid >> 4;
    const int lbn = (tid & 15) << 2;
    const int ty = tid >> 4;
    const int tx = tid & 15;
    float acc[4][4] = {};
    const int mA = m0 + lm;
    const bool mok = (mA < NN);
    const float invA = mok ? g_inv[mA] : 0.f;

    for (int kk = 0; kk < 512; kk += 16) {
        float4 a4 = make_float4(0.f, 0.f, 0.f, 0.f);
        if (mok) {
            if (kk < 256) {
                a4 = *(const float4*)(g_aggr + mA * HD + kk + lk);
                a4.x *= invA; a4.y *= invA; a4.z *= invA; a4.w *= invA;
            } else {
                a4 = *(const float4*)(hprev + mA * HD + (kk - 256) + lk);
            }
        }
        As[lk + 0][lm] = a4.x; As[lk + 1][lm] = a4.y;
        As[lk + 2][lm] = a4.z; As[lk + 3][lm] = a4.w;

        const float* W = (kk < 256) ? Wl : Wr;
        int kb = (kk & 255) + lbk;
        *(float4*)&Bs[lbk][lbn] = *(const float4*)(W + kb * HD + n0 + lbn);
        __syncthreads();
#pragma unroll
        for (int k = 0; k < 16; k++) {
            float4 a = *(const float4*)&As[k][ty << 2];
            float4 b = *(const float4*)&Bs[k][tx << 2];
            float av[4] = {a.x, a.y, a.z, a.w};
            float bv[4] = {b.x, b.y, b.z, b.w};
#pragma unroll
            for (int i = 0; i < 4; i++)
#pragma unroll
                for (int j = 0; j < 4; j++)
                    acc[i][j] += av[i] * bv[j];
        }
        __syncthreads();
    }
#pragma unroll
    for (int i = 0; i < 4; i++) {
        int m = m0 + (ty << 2) + i;
        if (m < NN) {
#pragma unroll
            for (int j = 0; j < 4; j++) {
                int n = n0 + (tx << 2) + j;
                hout[m * HD + n] = fmaxf(acc[i][j] + bl[n], 0.f);
            }
        }
    }
}

// Edge MLP layer 1: z1 = relu( [h[row], h[col], ea, td] @ W1 + b1 )
// M=NE, N=256, K=514 (padded to 528). A gathered on the fly from g_hA.
__global__ void k_mlp1(const float* __restrict__ ea,
                       const float* __restrict__ tdp, const float* __restrict__ W1,
                       const float* __restrict__ b1) {
    const float* h = g_hA;
    __shared__ float As[16][68];
    __shared__ float Bs[16][68];
    __shared__ int   rs[64], cs[64];
    __shared__ float eas[64];
    const int tid = threadIdx.x;
    const int m0 = blockIdx.x * 64;
    const int n0 = blockIdx.y * 64;
    if (tid < 64) {
        int m = m0 + tid;
        if (m < NE) { rs[tid] = g_row[m]; cs[tid] = g_col[m]; eas[tid] = ea[m]; }
        else        { rs[tid] = 0;        cs[tid] = 0;        eas[tid] = 0.f;  }
    }
    const float tdv = tdp[0];
    __syncthreads();

    const int lm  = tid >> 2;
    const int lk  = (tid & 3) << 2;
    const int lbk = tid >> 4;
    const int lbn = (tid & 15) << 2;
    const int ty = tid >> 4;
    const int tx = tid & 15;
    float acc[4][4] = {};

    for (int kk = 0; kk < 528; kk += 16) {
        int k = kk + lk;
        float4 a4;
        if (k < 256) {
            a4 = *(const float4*)(h + rs[lm] * HD + k);
        } else if (k < 512) {
            a4 = *(const float4*)(h + cs[lm] * HD + k - 256);
        } else {
            float v[4];
#pragma unroll
            for (int i = 0; i < 4; i++) {
                int kq = k + i;
                v[i] = (kq == 512) ? eas[lm] : ((kq == 513) ? tdv : 0.f);
            }
            a4 = make_float4(v[0], v[1], v[2], v[3]);
        }
        As[lk + 0][lm] = a4.x; As[lk + 1][lm] = a4.y;
        As[lk + 2][lm] = a4.z; As[lk + 3][lm] = a4.w;

        int kb = kk + lbk;
        float4 b4 = make_float4(0.f, 0.f, 0.f, 0.f);
        if (kb < 514) b4 = *(const float4*)(W1 + kb * HD + n0 + lbn);
        *(float4*)&Bs[lbk][lbn] = b4;
        __syncthreads();
#pragma unroll
        for (int k2 = 0; k2 < 16; k2++) {
            float4 a = *(const float4*)&As[k2][ty << 2];
            float4 b = *(const float4*)&Bs[k2][tx << 2];
            float av[4] = {a.x, a.y, a.z, a.w};
            float bv[4] = {b.x, b.y, b.z, b.w};
#pragma unroll
            for (int i = 0; i < 4; i++)
#pragma unroll
                for (int j = 0; j < 4; j++)
                    acc[i][j] += av[i] * bv[j];
        }
        __syncthreads();
    }
#pragma unroll
    for (int i = 0; i < 4; i++) {
        int m = m0 + (ty << 2) + i;
        if (m < NE) {
#pragma unroll
            for (int j = 0; j < 4; j++) {
                int n = n0 + (tx << 2) + j;
                g_z1[(size_t)m * HD + n] = fmaxf(acc[i][j] + b1[n], 0.f);
            }
        }
    }
}

// Edge MLP layers 2+3 fused: z2 = relu(z1 @ W2 + b2) [N=128 fully in-tile],
// then out = z2 @ W3 + b3. z2 never hits memory.
// 64x128 tile, 256 threads (4x8 per thread), BK=16.
__global__ void k_mlp2(const float* __restrict__ W2, const float* __restrict__ b2,
                       const float* __restrict__ W3, const float* __restrict__ b3,
                       float* __restrict__ out) {
    __shared__ float As[16][68];
    __shared__ float Bs[16][132];
    __shared__ float part[64][17];
    const int tid = threadIdx.x;
    const int m0 = blockIdx.x * 64;
    const int lm  = tid >> 2;
    const int lk  = (tid & 3) << 2;
    const int lbk = tid >> 4;        // 0..15
    const int lbn = (tid & 15) << 3; // 0..120
    const int ty = tid >> 4;
    const int tx = tid & 15;
    float acc[4][8] = {};
    const int mA = m0 + lm;
    const bool mok = (mA < NE);

    for (int kk = 0; kk < 256; kk += 16) {
        float4 a4 = make_float4(0.f, 0.f, 0.f, 0.f);
        if (mok) a4 = *(const float4*)(g_z1 + (size_t)mA * HD + kk + lk);
        As[lk + 0][lm] = a4.x; As[lk + 1][lm] = a4.y;
        As[lk + 2][lm] = a4.z; As[lk + 3][lm] = a4.w;

        *(float4*)&Bs[lbk][lbn]     = *(const float4*)(W2 + (kk + lbk) * 128 + lbn);
        *(float4*)&Bs[lbk][lbn + 4] = *(const float4*)(W2 + (kk + lbk) * 128 + lbn + 4);
        __syncthreads();
#pragma unroll
        for (int k = 0; k < 16; k++) {
            float4 a  = *(const float4*)&As[k][ty << 2];
            float4 b0 = *(const float4*)&Bs[k][tx << 3];
            float4 b1v = *(const float4*)&Bs[k][(tx << 3) + 4];
            float av[4] = {a.x, a.y, a.z, a.w};
            float bv[8] = {b0.x, b0.y, b0.z, b0.w, b1v.x, b1v.y, b1v.z, b1v.w};
#pragma unroll
            for (int i = 0; i < 4; i++)
#pragma unroll
                for (int j = 0; j < 8; j++)
                    acc[i][j] += av[i] * bv[j];
        }
        __syncthreads();
    }

    // fused epilogue: bias + relu + dot with W3, partial per thread
    float w3v[8], b2v[8];
#pragma unroll
    for (int j = 0; j < 8; j++) {
        w3v[j] = W3[(tx << 3) + j];
        b2v[j] = b2[(tx << 3) + j];
    }
#pragma unroll
    for (int i = 0; i < 4; i++) {
        float p = 0.f;
#pragma unroll
        for (int j = 0; j < 8; j++) {
            float z = fmaxf(acc[i][j] + b2v[j], 0.f);
            p += z * w3v[j];
        }
        part[(ty << 2) + i][tx] = p;
    }
    __syncthreads();
    if (tid < 64) {
        int m = m0 + tid;
        if (m < NE) {
            float s = b3[0];
#pragma unroll
            for (int t = 0; t < 16; t++) s += part[tid][t];
            out[m] = s;
        }
    }
}

// ---------------- host launcher ---------------------------------------------
extern "C" void kernel_launch(void* const* d_in, const int* in_sizes, int n_in,
                              void* d_out, int out_size) {
    const float* x   = (const float*)d_in[0];
    const void*  ei  = d_in[1];
    const float* ea  = (const float*)d_in[2];
    const float* td  = (const float*)d_in[3];
    const float* Wl1 = (const float*)d_in[4];
    const float* bl1 = (const float*)d_in[5];
    const float* Wr1 = (const float*)d_in[6];
    const float* Wl2 = (const float*)d_in[7];
    const float* bl2 = (const float*)d_in[8];
    const float* Wr2 = (const float*)d_in[9];
    const float* Wl3 = (const float*)d_in[10];
    const float* bl3 = (const float*)d_in[11];
    const float* Wr3 = (const float*)d_in[12];
    const float* W1  = (const float*)d_in[13];
    const float* b1  = (const float*)d_in[14];
    const float* W2  = (const float*)d_in[15];
    const float* b2  = (const float*)d_in[16];
    const float* W3  = (const float*)d_in[17];
    const float* b3  = (const float*)d_in[18];
    float* out = (float*)d_out;

    k_zero_small<<<160, 256>>>();
    k_detect<<<64, 256>>>((const int*)ei);
    k_idx_count<<<(NE + 255) / 256, 256>>>(ei);
    k_inv<<<(NN + 255) / 256, 256>>>();
    k_scatter3<<<(NE + 255) / 256, 256>>>(x);
    k_sage1<<<NN, 256>>>(x, Wl1, bl1, Wr1);           // -> g_hA

    dim3 gs(HD / 64, (NN + 63) / 64);

    // layer 2: read g_hA -> write g_hB
    k_zero_aggr<<<2048, 256>>>();
    k_scatter<<<(NE * 64) / 256, 256>>>(0);
    k_sage_gemm<<<gs, 256>>>(0, Wl2, Wr2, bl2);

    // layer 3: read g_hB -> write g_hA
    k_zero_aggr<<<2048, 256>>>();
    k_scatter<<<(NE * 64) / 256, 256>>>(1);
    k_sage_gemm<<<gs, 256>>>(1, Wl3, Wr3, bl3);

    // edge MLP (reads g_hA)
    dim3 g1((NE + 63) / 64, HD / 64);
    k_mlp1<<<g1, 256>>>(ea, td, W1, b1);              // -> g_z1
    k_mlp2<<<(NE + 63) / 64, 256>>>(W2, b2, W3, b3, out);
}

// round 6
// speedup vs baseline: 3.6790x; 3.6790x over previous
#include <cuda_runtime.h>
#include <cstdint>

#define NN 20000
#define NE 300000
#define HD 256

// ---------------- scratch (device globals; referenced ONLY in device code) --
__device__ __align__(16) float g_cnt[NN];
__device__ __align__(16) float g_inv[NN];
__device__ __align__(16) float g_aggr3[NN * 4];
__device__ __align__(16) float g_aggr[NN * HD];   // aggr; later reused as P2
__device__ __align__(16) float g_hA[NN * HD];
__device__ __align__(16) float g_hB[NN * HD];     // layer2 h; later reused as P1
__device__ int g_row[NE];
__device__ int g_col[NE];
__device__ int g_is64;

__device__ __forceinline__ float to_tf32(float x) {
    uint32_t u;
    asm("cvt.rna.tf32.f32 %0, %1;" : "=r"(u) : "f"(x));
    return __uint_as_float(u);
}

// ---------------- small utility kernels ------------------------------------
__global__ void k_zero_small() {
    int i = blockIdx.x * blockDim.x + threadIdx.x;
    int stride = gridDim.x * blockDim.x;
    if (i == 0) g_is64 = 1;
    for (int j = i; j < NN; j += stride) g_cnt[j] = 0.f;
    for (int j = i; j < NN * 4; j += stride) g_aggr3[j] = 0.f;
}

// Detect edge_index dtype (int64 vs int32). Safe under both interpretations.
__global__ void k_detect(const int* __restrict__ ei32) {
    int i = blockIdx.x * blockDim.x + threadIdx.x;
    int stride = gridDim.x * blockDim.x;
    for (int e = i; e < NE; e += stride) {
        if (ei32[2 * e + 1] != 0) { g_is64 = 0; break; }
    }
}

__global__ void k_zero_aggr() {
    int i = blockIdx.x * blockDim.x + threadIdx.x;
    int stride = gridDim.x * blockDim.x;
    for (int j = i; j < NN * HD / 4; j += stride)
        ((float4*)g_aggr)[j] = make_float4(0.f, 0.f, 0.f, 0.f);
}

__global__ void k_idx_count(const void* __restrict__ eiv) {
    int e = blockIdx.x * blockDim.x + threadIdx.x;
    if (e < NE) {
        int r, c;
        if (g_is64) {
            const long long* ei = (const long long*)eiv;
            r = (int)ei[e];
            c = (int)ei[NE + e];
        } else {
            const int* ei = (const int*)eiv;
            r = ei[e];
            c = ei[NE + e];
        }
        r = min(max(r, 0), NN - 1);
        c = min(max(c, 0), NN - 1);
        g_row[e] = r;
        g_col[e] = c;
        atomicAdd(&g_cnt[c], 1.f);
    }
}

__global__ void k_inv() {
    int n = blockIdx.x * blockDim.x + threadIdx.x;
    if (n < NN) g_inv[n] = 1.f / fmaxf(g_cnt[n], 1.f);
}

__global__ void k_scatter3(const float* __restrict__ x) {
    int e = blockIdx.x * blockDim.x + threadIdx.x;
    if (e < NE) {
        int r = g_row[e], c = g_col[e];
        atomicAdd(&g_aggr3[4 * c + 0], x[3 * r + 0]);
        atomicAdd(&g_aggr3[4 * c + 1], x[3 * r + 1]);
        atomicAdd(&g_aggr3[4 * c + 2], x[3 * r + 2]);
    }
}

// Layer 1: d_in = 3. Writes g_hA.
__global__ void k_sage1(const float* __restrict__ x, const float* __restrict__ Wl,
                        const float* __restrict__ bl, const float* __restrict__ Wr) {
    int n = blockIdx.x;
    int j = threadIdx.x;
    __shared__ float a[3], xs[3];
    if (j < 3) {
        a[j]  = g_aggr3[4 * n + j] * g_inv[n];
        xs[j] = x[3 * n + j];
    }
    __syncthreads();
    float v = bl[j];
#pragma unroll
    for (int d = 0; d < 3; d++)
        v += a[d] * Wl[d * HD + j] + xs[d] * Wr[d * HD + j];
    g_hA[n * HD + j] = fmaxf(v, 0.f);
}

// Scatter-add h[row[e]] into g_aggr[col[e]], vector red.v4 (sm_90a+).
__global__ void k_scatter(int src) {
    const float* h = src ? g_hB : g_hA;
    int t = blockIdx.x * blockDim.x + threadIdx.x;  // 0 .. NE*64-1
    int e = t >> 6;
    int q = (t & 63) << 2;
    if (e < NE) {
        int r = g_row[e], c = g_col[e];
        float4 v = *(const float4*)(h + r * HD + q);
        float* dst = g_aggr + c * HD + q;
        asm volatile("red.global.add.v4.f32 [%0], {%1,%2,%3,%4};"
                     :: "l"(dst), "f"(v.x), "f"(v.y), "f"(v.z), "f"(v.w)
                     : "memory");
    }
}

// Fused dual-GEMM SAGE layer: hout = relu( (aggr*inv) @ Wl + hprev @ Wr + bl )
__global__ void k_sage_gemm(int src, const float* __restrict__ Wl,
                            const float* __restrict__ Wr, const float* __restrict__ bl) {
    const float* hprev = src ? g_hB : g_hA;
    float*       hout  = src ? g_hA : g_hB;
    __shared__ float As[16][68];
    __shared__ float Bs[16][68];
    const int tid = threadIdx.x;
    const int m0 = blockIdx.y * 64;
    const int n0 = blockIdx.x * 64;
    const int lm  = tid >> 2;
    const int lk  = (tid & 3) << 2;
    const int lbk = tid >> 4;
    const int lbn = (tid & 15) << 2;
    const int ty = tid >> 4;
    const int tx = tid & 15;
    float acc[4][4] = {};
    const int mA = m0 + lm;
    const bool mok = (mA < NN);
    const float invA = mok ? g_inv[mA] : 0.f;

    for (int kk = 0; kk < 512; kk += 16) {
        float4 a4 = make_float4(0.f, 0.f, 0.f, 0.f);
        if (mok) {
            if (kk < 256) {
                a4 = *(const float4*)(g_aggr + mA * HD + kk + lk);
                a4.x *= invA; a4.y *= invA; a4.z *= invA; a4.w *= invA;
            } else {
                a4 = *(const float4*)(hprev + mA * HD + (kk - 256) + lk);
            }
        }
        As[lk + 0][lm] = a4.x; As[lk + 1][lm] = a4.y;
        As[lk + 2][lm] = a4.z; As[lk + 3][lm] = a4.w;

        const float* W = (kk < 256) ? Wl : Wr;
        int kb = (kk & 255) + lbk;
        *(float4*)&Bs[lbk][lbn] = *(const float4*)(W + kb * HD + n0 + lbn);
        __syncthreads();
#pragma unroll
        for (int k = 0; k < 16; k++) {
            float4 a = *(const float4*)&As[k][ty << 2];
            float4 b = *(const float4*)&Bs[k][tx << 2];
            float av[4] = {a.x, a.y, a.z, a.w};
            float bv[4] = {b.x, b.y, b.z, b.w};
#pragma unroll
            for (int i = 0; i < 4; i++)
#pragma unroll
                for (int j = 0; j < 4; j++)
                    acc[i][j] += av[i] * bv[j];
        }
        __syncthreads();
    }
#pragma unroll
    for (int i = 0; i < 4; i++) {
        int m = m0 + (ty << 2) + i;
        if (m < NN) {
#pragma unroll
            for (int j = 0; j < 4; j++) {
                int n = n0 + (tx << 2) + j;
                hout[m * HD + n] = fmaxf(acc[i][j] + bl[n], 0.f);
            }
        }
    }
}

// Plain GEMM: out = g_hA @ B  (M=NN, N=256, K=256). dst: 0 -> g_hB (P1),
// 1 -> g_aggr (P2). No bias/relu.
__global__ void k_proj(int dst, const float* __restrict__ B) {
    const float* hsrc = g_hA;
    float* outp = dst ? g_aggr : g_hB;
    __shared__ float As[16][68];
    __shared__ float Bs[16][68];
    const int tid = threadIdx.x;
    const int m0 = blockIdx.y * 64;
    const int n0 = blockIdx.x * 64;
    const int lm  = tid >> 2;
    const int lk  = (tid & 3) << 2;
    const int lbk = tid >> 4;
    const int lbn = (tid & 15) << 2;
    const int ty = tid >> 4;
    const int tx = tid & 15;
    float acc[4][4] = {};
    const int mA = m0 + lm;
    const bool mok = (mA < NN);

    for (int kk = 0; kk < 256; kk += 16) {
        float4 a4 = make_float4(0.f, 0.f, 0.f, 0.f);
        if (mok) a4 = *(const float4*)(hsrc + mA * HD + kk + lk);
        As[lk + 0][lm] = a4.x; As[lk + 1][lm] = a4.y;
        As[lk + 2][lm] = a4.z; As[lk + 3][lm] = a4.w;
        *(float4*)&Bs[lbk][lbn] = *(const float4*)(B + (kk + lbk) * HD + n0 + lbn);
        __syncthreads();
#pragma unroll
        for (int k = 0; k < 16; k++) {
            float4 a = *(const float4*)&As[k][ty << 2];
            float4 b = *(const float4*)&Bs[k][tx << 2];
            float av[4] = {a.x, a.y, a.z, a.w};
            float bv[4] = {b.x, b.y, b.z, b.w};
#pragma unroll
            for (int i = 0; i < 4; i++)
#pragma unroll
                for (int j = 0; j < 4; j++)
                    acc[i][j] += av[i] * bv[j];
        }
        __syncthreads();
    }
#pragma unroll
    for (int i = 0; i < 4; i++) {
        int m = m0 + (ty << 2) + i;
        if (m < NN) {
#pragma unroll
            for (int j = 0; j < 4; j++)
                outp[m * HD + n0 + (tx << 2) + j] = acc[i][j];
        }
    }
}

// Fused edge kernel (tf32 tensor cores):
//   z1 = relu(P1[row] + P2[col] + ea*w512 + td*w513 + b1)   (A tile, on the fly)
//   z2 = relu(z1 @ W2 + b2)                                  (mma.sync tf32)
//   out = z2 @ W3 + b3                                       (in-register epilogue)
// Tile: 64 edges x N=128, K=256 chunked by 32. 256 threads = 8 warps:
// warp w handles rows (w>>1)*16..+16, cols (w&1)*64..+64 (8 n-blocks of 8).
__global__ void k_edge(const float* __restrict__ ea, const float* __restrict__ tdp,
                       const float* __restrict__ W1, const float* __restrict__ b1,
                       const float* __restrict__ W2, const float* __restrict__ b2,
                       const float* __restrict__ W3, const float* __restrict__ b3,
                       float* __restrict__ out) {
    __shared__ float As[64][33];
    __shared__ float Bs[32][132];
    __shared__ int   rs[64], cs[64];
    __shared__ float eas[64];
    __shared__ float w512s[256], bases[256];
    __shared__ float part[64][2];

    const int tid = threadIdx.x;
    const int m0 = blockIdx.x * 64;
    const float tdv = tdp[0];

    if (tid < 64) {
        int m = m0 + tid;
        if (m < NE) { rs[tid] = g_row[m]; cs[tid] = g_col[m]; eas[tid] = ea[m]; }
        else        { rs[tid] = 0;        cs[tid] = 0;        eas[tid] = 0.f;  }
    }
    for (int k = tid; k < 256; k += 256) {
        w512s[k] = W1[512 * HD + k];
        bases[k] = b1[k] + tdv * W1[513 * HD + k];
    }
    __syncthreads();

    const int lane = tid & 31;
    const int wid  = tid >> 5;
    const int mblk = wid >> 1;          // 0..3
    const int nhalf = wid & 1;          // 0..1
    float acc[8][4] = {};

    // A-construction mapping: row = tid>>2, k-segment = (tid&3)*8
    const int arow = tid >> 2;
    const int ak   = (tid & 3) << 3;
    const float* p1r = g_hB   + (size_t)rs[arow] * HD;
    const float* p2r = g_aggr + (size_t)cs[arow] * HD;
    const float eav = eas[arow];

    for (int kk = 0; kk < 256; kk += 32) {
        // load W2 chunk [32 x 128] (converted to tf32-rna)
#pragma unroll
        for (int p = 0; p < 4; p++) {
            int r = (tid >> 5) + p * 8;
            int c4 = lane * 4;
            float4 w = *(const float4*)(W2 + (kk + r) * 128 + c4);
            Bs[r][c4 + 0] = to_tf32(w.x);
            Bs[r][c4 + 1] = to_tf32(w.y);
            Bs[r][c4 + 2] = to_tf32(w.z);
            Bs[r][c4 + 3] = to_tf32(w.w);
        }
        // construct A chunk [64 x 32] (z1 values, converted to tf32-rna)
        {
            float4 u  = *(const float4*)(p1r + kk + ak);
            float4 v  = *(const float4*)(p2r + kk + ak);
            float4 u2 = *(const float4*)(p1r + kk + ak + 4);
            float4 v2 = *(const float4*)(p2r + kk + ak + 4);
            int kb = kk + ak;
            As[arow][ak + 0] = to_tf32(fmaxf(u.x  + v.x  + eav * w512s[kb + 0] + bases[kb + 0], 0.f));
            As[arow][ak + 1] = to_tf32(fmaxf(u.y  + v.y  + eav * w512s[kb + 1] + bases[kb + 1], 0.f));
            As[arow][ak + 2] = to_tf32(fmaxf(u.z  + v.z  + eav * w512s[kb + 2] + bases[kb + 2], 0.f));
            As[arow][ak + 3] = to_tf32(fmaxf(u.w  + v.w  + eav * w512s[kb + 3] + bases[kb + 3], 0.f));
            As[arow][ak + 4] = to_tf32(fmaxf(u2.x + v2.x + eav * w512s[kb + 4] + bases[kb + 4], 0.f));
            As[arow][ak + 5] = to_tf32(fmaxf(u2.y + v2.y + eav * w512s[kb + 5] + bases[kb + 5], 0.f));
            As[arow][ak + 6] = to_tf32(fmaxf(u2.z + v2.z + eav * w512s[kb + 6] + bases[kb + 6], 0.f));
            As[arow][ak + 7] = to_tf32(fmaxf(u2.w + v2.w + eav * w512s[kb + 7] + bases[kb + 7], 0.f));
        }
        __syncthreads();
#pragma unroll
        for (int ks = 0; ks < 4; ks++) {
            int kb = ks * 8;
            int r0 = mblk * 16 + (lane >> 2);
            // PTX m16n8k8 tf32 A-fragment order:
            // a0=(g,t) a1=(g+8,t) a2=(g,t+4) a3=(g+8,t+4)
            uint32_t a0 = __float_as_uint(As[r0][kb + (lane & 3)]);
            uint32_t a1 = __float_as_uint(As[r0 + 8][kb + (lane & 3)]);
            uint32_t a2 = __float_as_uint(As[r0][kb + (lane & 3) + 4]);
            uint32_t a3 = __float_as_uint(As[r0 + 8][kb + (lane & 3) + 4]);
#pragma unroll
            for (int nb = 0; nb < 8; nb++) {
                int nc = nhalf * 64 + nb * 8 + (lane >> 2);
                uint32_t b0 = __float_as_uint(Bs[kb + (lane & 3)][nc]);
                uint32_t b1r = __float_as_uint(Bs[kb + (lane & 3) + 4][nc]);
                asm volatile(
                    "mma.sync.aligned.m16n8k8.row.col.f32.tf32.tf32.f32 "
                    "{%0,%1,%2,%3}, {%4,%5,%6,%7}, {%8,%9}, {%0,%1,%2,%3};"
                    : "+f"(acc[nb][0]), "+f"(acc[nb][1]), "+f"(acc[nb][2]), "+f"(acc[nb][3])
                    : "r"(a0), "r"(a1), "r"(a2), "r"(a3), "r"(b0), "r"(b1r));
            }
        }
        __syncthreads();
    }

    // epilogue: relu(acc + b2) dot W3, quad reduce
    float pr0 = 0.f, pr1 = 0.f;
#pragma unroll
    for (int nb = 0; nb < 8; nb++) {
        int ncol = nhalf * 64 + nb * 8 + 2 * (lane & 3);
        float w3a = W3[ncol], w3b = W3[ncol + 1];
        float b2a = b2[ncol], b2b = b2[ncol + 1];
        pr0 += fmaxf(acc[nb][0] + b2a, 0.f) * w3a + fmaxf(acc[nb][1] + b2b, 0.f) * w3b;
        pr1 += fmaxf(acc[nb][2] + b2a, 0.f) * w3a + fmaxf(acc[nb][3] + b2b, 0.f) * w3b;
    }
    pr0 += __shfl_xor_sync(0xffffffff, pr0, 1);
    pr0 += __shfl_xor_sync(0xffffffff, pr0, 2);
    pr1 += __shfl_xor_sync(0xffffffff, pr1, 1);
    pr1 += __shfl_xor_sync(0xffffffff, pr1, 2);
    if ((lane & 3) == 0) {
        part[mblk * 16 + (lane >> 2)][nhalf]     = pr0;
        part[mblk * 16 + (lane >> 2) + 8][nhalf] = pr1;
    }
    __syncthreads();
    if (tid < 64) {
        int m = m0 + tid;
        if (m < NE) out[m] = part[tid][0] + part[tid][1] + b3[0];
    }
}

// ---------------- host launcher ---------------------------------------------
extern "C" void kernel_launch(void* const* d_in, const int* in_sizes, int n_in,
                              void* d_out, int out_size) {
    const float* x   = (const float*)d_in[0];
    const void*  ei  = d_in[1];
    const float* ea  = (const float*)d_in[2];
    const float* td  = (const float*)d_in[3];
    const float* Wl1 = (const float*)d_in[4];
    const float* bl1 = (const float*)d_in[5];
    const float* Wr1 = (const float*)d_in[6];
    const float* Wl2 = (const float*)d_in[7];
    const float* bl2 = (const float*)d_in[8];
    const float* Wr2 = (const float*)d_in[9];
    const float* Wl3 = (const float*)d_in[10];
    const float* bl3 = (const float*)d_in[11];
    const float* Wr3 = (const float*)d_in[12];
    const float* W1  = (const float*)d_in[13];
    const float* b1  = (const float*)d_in[14];
    const float* W2  = (const float*)d_in[15];
    const float* b2  = (const float*)d_in[16];
    const float* W3  = (const float*)d_in[17];
    const float* b3  = (const float*)d_in[18];
    float* out = (float*)d_out;

    k_zero_small<<<160, 256>>>();
    k_detect<<<64, 256>>>((const int*)ei);
    k_idx_count<<<(NE + 255) / 256, 256>>>(ei);
    k_inv<<<(NN + 255) / 256, 256>>>();
    k_scatter3<<<(NE + 255) / 256, 256>>>(x);
    k_sage1<<<NN, 256>>>(x, Wl1, bl1, Wr1);           // -> g_hA

    dim3 gs(HD / 64, (NN + 63) / 64);

    // layer 2: read g_hA -> write g_hB
    k_zero_aggr<<<2048, 256>>>();
    k_scatter<<<(NE * 64) / 256, 256>>>(0);
    k_sage_gemm<<<gs, 256>>>(0, Wl2, Wr2, bl2);

    // layer 3: read g_hB -> write g_hA
    k_zero_aggr<<<2048, 256>>>();
    k_scatter<<<(NE * 64) / 256, 256>>>(1);
    k_sage_gemm<<<gs, 256>>>(1, Wl3, Wr3, bl3);

    // node projections: P1 = h @ W1[0:256]  -> g_hB
    //                   P2 = h @ W1[256:512] -> g_aggr
    k_proj<<<gs, 256>>>(0, W1);
    k_proj<<<gs, 256>>>(1, W1 + 256 * HD);

    // fused edge MLP (tf32 mma)
    k_edge<<<(NE + 63) / 64, 256>>>(ea, td, W1, b1, W2, b2, W3, b3, out);
}

// round 7
// speedup vs baseline: 3.9129x; 1.0636x over previous
#include <cuda_runtime.h>
#include <cstdint>

#define NN 20000
#define NE 300000
#define HD 256

// ---------------- scratch (device globals; referenced ONLY in device code) --
__device__ __align__(16) float g_cnt[NN];
__device__ __align__(16) float g_inv[NN];
__device__ __align__(16) float g_aggr3[NN * 4];
__device__ __align__(16) float g_aggr[NN * HD];   // aggr; later reused as P2
__device__ __align__(16) float g_hA[NN * HD];
__device__ __align__(16) float g_hB[NN * HD];     // layer2 h; later reused as P1
__device__ int g_row[NE];
__device__ int g_col[NE];
__device__ int g_is64;

__device__ __forceinline__ float to_tf32(float x) {
    uint32_t u;
    asm("cvt.rna.tf32.f32 %0, %1;" : "=r"(u) : "f"(x));
    return __uint_as_float(u);
}

#define MMA_TF32(acc, a0, a1, a2, a3, b0, b1)                                   \
    asm volatile(                                                               \
        "mma.sync.aligned.m16n8k8.row.col.f32.tf32.tf32.f32 "                   \
        "{%0,%1,%2,%3}, {%4,%5,%6,%7}, {%8,%9}, {%0,%1,%2,%3};"                 \
        : "+f"(acc[0]), "+f"(acc[1]), "+f"(acc[2]), "+f"(acc[3])                \
        : "r"(a0), "r"(a1), "r"(a2), "r"(a3), "r"(b0), "r"(b1))

// ---------------- small utility kernels ------------------------------------
__global__ void k_zero_small() {
    int i = blockIdx.x * blockDim.x + threadIdx.x;
    int stride = gridDim.x * blockDim.x;
    if (i == 0) g_is64 = 1;
    for (int j = i; j < NN; j += stride) g_cnt[j] = 0.f;
    for (int j = i; j < NN * 4; j += stride) g_aggr3[j] = 0.f;
}

// Detect edge_index dtype (int64 vs int32). Safe under both interpretations.
__global__ void k_detect(const int* __restrict__ ei32) {
    int i = blockIdx.x * blockDim.x + threadIdx.x;
    int stride = gridDim.x * blockDim.x;
    for (int e = i; e < NE; e += stride) {
        if (ei32[2 * e + 1] != 0) { g_is64 = 0; break; }
    }
}

__global__ void k_zero_aggr() {
    int i = blockIdx.x * blockDim.x + threadIdx.x;
    int stride = gridDim.x * blockDim.x;
    for (int j = i; j < NN * HD / 4; j += stride)
        ((float4*)g_aggr)[j] = make_float4(0.f, 0.f, 0.f, 0.f);
}

__global__ void k_idx_count(const void* __restrict__ eiv) {
    int e = blockIdx.x * blockDim.x + threadIdx.x;
    if (e < NE) {
        int r, c;
        if (g_is64) {
            const long long* ei = (const long long*)eiv;
            r = (int)ei[e];
            c = (int)ei[NE + e];
        } else {
            const int* ei = (const int*)eiv;
            r = ei[e];
            c = ei[NE + e];
        }
        r = min(max(r, 0), NN - 1);
        c = min(max(c, 0), NN - 1);
        g_row[e] = r;
        g_col[e] = c;
        atomicAdd(&g_cnt[c], 1.f);
    }
}

__global__ void k_inv() {
    int n = blockIdx.x * blockDim.x + threadIdx.x;
    if (n < NN) g_inv[n] = 1.f / fmaxf(g_cnt[n], 1.f);
}

__global__ void k_scatter3(const float* __restrict__ x) {
    int e = blockIdx.x * blockDim.x + threadIdx.x;
    if (e < NE) {
        int r = g_row[e], c = g_col[e];
        atomicAdd(&g_aggr3[4 * c + 0], x[3 * r + 0]);
        atomicAdd(&g_aggr3[4 * c + 1], x[3 * r + 1]);
        atomicAdd(&g_aggr3[4 * c + 2], x[3 * r + 2]);
    }
}

// Layer 1: d_in = 3. Writes g_hA.
__global__ void k_sage1(const float* __restrict__ x, const float* __restrict__ Wl,
                        const float* __restrict__ bl, const float* __restrict__ Wr) {
    int n = blockIdx.x;
    int j = threadIdx.x;
    __shared__ float a[3], xs[3];
    if (j < 3) {
        a[j]  = g_aggr3[4 * n + j] * g_inv[n];
        xs[j] = x[3 * n + j];
    }
    __syncthreads();
    float v = bl[j];
#pragma unroll
    for (int d = 0; d < 3; d++)
        v += a[d] * Wl[d * HD + j] + xs[d] * Wr[d * HD + j];
    g_hA[n * HD + j] = fmaxf(v, 0.f);
}

// Scatter-add h[row[e]] into g_aggr[col[e]], vector red.v4 (sm_90a+).
__global__ void k_scatter(int src) {
    const float* h = src ? g_hB : g_hA;
    int t = blockIdx.x * blockDim.x + threadIdx.x;  // 0 .. NE*64-1
    int e = t >> 6;
    int q = (t & 63) << 2;
    if (e < NE) {
        int r = g_row[e], c = g_col[e];
        float4 v = *(const float4*)(h + r * HD + q);
        float* dst = g_aggr + c * HD + q;
        asm volatile("red.global.add.v4.f32 [%0], {%1,%2,%3,%4};"
                     :: "l"(dst), "f"(v.x), "f"(v.y), "f"(v.z), "f"(v.w)
                     : "memory");
    }
}

// ---------------------------------------------------------------------------
// Tensor-core SAGE layer (3xTF32 split precision, fp32-quality):
//   hout = relu( (aggr*inv) @ Wl + hprev @ Wr + bl )
// M=NN, N=256, virtual K=512. Tile 64x128, 8 warps, BK=32.
// Warp w: rows (w>>1)*16..+16, cols (w&1)*64..+64 (8 n8-blocks).
// Dynamic smem: Ah[64][36], Al[64][36], Bh[32][132], Bl[32][132].
// ---------------------------------------------------------------------------
__global__ void k_sage_tc(int src, const float* __restrict__ Wl,
                          const float* __restrict__ Wr, const float* __restrict__ bl) {
    const float* hprev = src ? g_hB : g_hA;
    float*       hout  = src ? g_hA : g_hB;
    extern __shared__ float sm[];
    float* Ah = sm;                 // 64*36 = 2304
    float* Al = sm + 2304;
    float* Bh = sm + 4608;          // 32*132 = 4224
    float* Bl = sm + 8832;

    const int tid = threadIdx.x;
    const int m0 = blockIdx.y * 64;
    const int n0 = blockIdx.x * 128;
    const int lane = tid & 31, wid = tid >> 5;
    const int mblk = wid >> 1, nhalf = wid & 1;
    const int g = lane >> 2, t = lane & 3;
    const int arow = tid >> 2, ak = (tid & 3) << 3;
    const int mA = m0 + arow;
    const bool mok = (mA < NN);
    const float invA = mok ? g_inv[mA] : 0.f;
    const float* aggp = g_aggr + (size_t)mA * HD;
    const float* hpp  = hprev  + (size_t)mA * HD;
    float acc[8][4] = {};

    for (int kk = 0; kk < 512; kk += 32) {
        // ---- A fill (hi/lo split)
        {
            float v[8];
            if (mok) {
                const float* p = (kk < 256) ? (aggp + kk + ak) : (hpp + (kk - 256) + ak);
                float4 u  = *(const float4*)p;
                float4 u2 = *(const float4*)(p + 4);
                float s = (kk < 256) ? invA : 1.f;
                v[0] = u.x * s;  v[1] = u.y * s;  v[2] = u.z * s;  v[3] = u.w * s;
                v[4] = u2.x * s; v[5] = u2.y * s; v[6] = u2.z * s; v[7] = u2.w * s;
            } else {
#pragma unroll
                for (int i = 0; i < 8; i++) v[i] = 0.f;
            }
#pragma unroll
            for (int i = 0; i < 8; i++) {
                float hi = to_tf32(v[i]);
                Ah[arow * 36 + ak + i] = hi;
                Al[arow * 36 + ak + i] = to_tf32(v[i] - hi);
            }
        }
        // ---- B fill (hi/lo split)
        {
            const float* W = (kk < 256) ? Wl : Wr;
            int kbase = kk & 255;
#pragma unroll
            for (int p = 0; p < 4; p++) {
                int r = wid + p * 8;
                int c = lane * 4;
                float4 w = *(const float4*)(W + (kbase + r) * HD + n0 + c);
                float h0 = to_tf32(w.x), h1 = to_tf32(w.y), h2 = to_tf32(w.z), h3 = to_tf32(w.w);
                Bh[r * 132 + c + 0] = h0; Bl[r * 132 + c + 0] = to_tf32(w.x - h0);
                Bh[r * 132 + c + 1] = h1; Bl[r * 132 + c + 1] = to_tf32(w.y - h1);
                Bh[r * 132 + c + 2] = h2; Bl[r * 132 + c + 2] = to_tf32(w.z - h2);
                Bh[r * 132 + c + 3] = h3; Bl[r * 132 + c + 3] = to_tf32(w.w - h3);
            }
        }
        __syncthreads();
#pragma unroll
        for (int ks = 0; ks < 4; ks++) {
            int kb = ks * 8;
            int r0 = mblk * 16 + g;
            uint32_t ah0 = __float_as_uint(Ah[r0 * 36 + kb + t]);
            uint32_t ah1 = __float_as_uint(Ah[(r0 + 8) * 36 + kb + t]);
            uint32_t ah2 = __float_as_uint(Ah[r0 * 36 + kb + t + 4]);
            uint32_t ah3 = __float_as_uint(Ah[(r0 + 8) * 36 + kb + t + 4]);
            uint32_t al0 = __float_as_uint(Al[r0 * 36 + kb + t]);
            uint32_t al1 = __float_as_uint(Al[(r0 + 8) * 36 + kb + t]);
            uint32_t al2 = __float_as_uint(Al[r0 * 36 + kb + t + 4]);
            uint32_t al3 = __float_as_uint(Al[(r0 + 8) * 36 + kb + t + 4]);
#pragma unroll
            for (int nb = 0; nb < 8; nb++) {
                int nc = nhalf * 64 + nb * 8 + g;
                uint32_t bh0 = __float_as_uint(Bh[(kb + t) * 132 + nc]);
                uint32_t bh1 = __float_as_uint(Bh[(kb + t + 4) * 132 + nc]);
                uint32_t bl0 = __float_as_uint(Bl[(kb + t) * 132 + nc]);
                uint32_t bl1 = __float_as_uint(Bl[(kb + t + 4) * 132 + nc]);
                MMA_TF32(acc[nb], ah0, ah1, ah2, ah3, bh0, bh1);
                MMA_TF32(acc[nb], ah0, ah1, ah2, ah3, bl0, bl1);
                MMA_TF32(acc[nb], al0, al1, al2, al3, bh0, bh1);
            }
        }
        __syncthreads();
    }
    // epilogue: bias + relu
    int row0 = m0 + mblk * 16 + g;
#pragma unroll
    for (int nb = 0; nb < 8; nb++) {
        int col = n0 + nhalf * 64 + nb * 8 + 2 * t;
        float bla = bl[col], blb = bl[col + 1];
        if (row0 < NN) {
            hout[row0 * HD + col]     = fmaxf(acc[nb][0] + bla, 0.f);
            hout[row0 * HD + col + 1] = fmaxf(acc[nb][1] + blb, 0.f);
        }
        if (row0 + 8 < NN) {
            hout[(row0 + 8) * HD + col]     = fmaxf(acc[nb][2] + bla, 0.f);
            hout[(row0 + 8) * HD + col + 1] = fmaxf(acc[nb][3] + blb, 0.f);
        }
    }
}

// ---------------------------------------------------------------------------
// Fused projection GEMM (3xTF32): [P1 | P2] = g_hA @ [W1a | W1b]
// M=NN, N=512 (n<256 -> P1 in g_hB, n>=256 -> P2 in g_aggr), K=256.
// Same tiling as k_sage_tc.
// ---------------------------------------------------------------------------
__global__ void k_proj_tc(const float* __restrict__ W1) {
    extern __shared__ float sm[];
    float* Ah = sm;
    float* Al = sm + 2304;
    float* Bh = sm + 4608;
    float* Bl = sm + 8832;

    const int tid = threadIdx.x;
    const int m0 = blockIdx.y * 64;
    const int n0 = blockIdx.x * 128;
    const int lane = tid & 31, wid = tid >> 5;
    const int mblk = wid >> 1, nhalf = wid & 1;
    const int g = lane >> 2, t = lane & 3;
    const int arow = tid >> 2, ak = (tid & 3) << 3;
    const int mA = m0 + arow;
    const bool mok = (mA < NN);
    const float* hp = g_hA + (size_t)mA * HD;
    float acc[8][4] = {};

    for (int kk = 0; kk < 256; kk += 32) {
        {
            float v[8];
            if (mok) {
                float4 u  = *(const float4*)(hp + kk + ak);
                float4 u2 = *(const float4*)(hp + kk + ak + 4);
                v[0] = u.x;  v[1] = u.y;  v[2] = u.z;  v[3] = u.w;
                v[4] = u2.x; v[5] = u2.y; v[6] = u2.z; v[7] = u2.w;
            } else {
#pragma unroll
                for (int i = 0; i < 8; i++) v[i] = 0.f;
            }
#pragma unroll
            for (int i = 0; i < 8; i++) {
                float hi = to_tf32(v[i]);
                Ah[arow * 36 + ak + i] = hi;
                Al[arow * 36 + ak + i] = to_tf32(v[i] - hi);
            }
        }
        {
#pragma unroll
            for (int p = 0; p < 4; p++) {
                int r = wid + p * 8;
                int c = lane * 4;
                int n = n0 + c;                       // 0..508
                int rowoff = (n >= 256) ? 256 : 0;    // whole float4 same half
                float4 w = *(const float4*)(W1 + (size_t)(kk + r + rowoff) * HD + (n & 255));
                float h0 = to_tf32(w.x), h1 = to_tf32(w.y), h2 = to_tf32(w.z), h3 = to_tf32(w.w);
                Bh[r * 132 + c + 0] = h0; Bl[r * 132 + c + 0] = to_tf32(w.x - h0);
                Bh[r * 132 + c + 1] = h1; Bl[r * 132 + c + 1] = to_tf32(w.y - h1);
                Bh[r * 132 + c + 2] = h2; Bl[r * 132 + c + 2] = to_tf32(w.z - h2);
                Bh[r * 132 + c + 3] = h3; Bl[r * 132 + c + 3] = to_tf32(w.w - h3);
            }
        }
        __syncthreads();
#pragma unroll
        for (int ks = 0; ks < 4; ks++) {
            int kb = ks * 8;
            int r0 = mblk * 16 + g;
            uint32_t ah0 = __float_as_uint(Ah[r0 * 36 + kb + t]);
            uint32_t ah1 = __float_as_uint(Ah[(r0 + 8) * 36 + kb + t]);
            uint32_t ah2 = __float_as_uint(Ah[r0 * 36 + kb + t + 4]);
            uint32_t ah3 = __float_as_uint(Ah[(r0 + 8) * 36 + kb + t + 4]);
            uint32_t al0 = __float_as_uint(Al[r0 * 36 + kb + t]);
            uint32_t al1 = __float_as_uint(Al[(r0 + 8) * 36 + kb + t]);
            uint32_t al2 = __float_as_uint(Al[r0 * 36 + kb + t + 4]);
            uint32_t al3 = __float_as_uint(Al[(r0 + 8) * 36 + kb + t + 4]);
#pragma unroll
            for (int nb = 0; nb < 8; nb++) {
                int nc = nhalf * 64 + nb * 8 + g;
                uint32_t bh0 = __float_as_uint(Bh[(kb + t) * 132 + nc]);
                uint32_t bh1 = __float_as_uint(Bh[(kb + t + 4) * 132 + nc]);
                uint32_t bl0 = __float_as_uint(Bl[(kb + t) * 132 + nc]);
                uint32_t bl1 = __float_as_uint(Bl[(kb + t + 4) * 132 + nc]);
                MMA_TF32(acc[nb], ah0, ah1, ah2, ah3, bh0, bh1);
                MMA_TF32(acc[nb], ah0, ah1, ah2, ah3, bl0, bl1);
                MMA_TF32(acc[nb], al0, al1, al2, al3, bh0, bh1);
            }
        }
        __syncthreads();
    }
    int row0 = m0 + mblk * 16 + g;
#pragma unroll
    for (int nb = 0; nb < 8; nb++) {
        int col = n0 + nhalf * 64 + nb * 8 + 2 * t;   // global n, 0..511
        float* dst = (col < 256) ? (g_hB + col) : (g_aggr + col - 256);
        if (row0 < NN) {
            dst[row0 * HD]     = acc[nb][0];
            dst[row0 * HD + 1] = acc[nb][1];
        }
        if (row0 + 8 < NN) {
            dst[(row0 + 8) * HD]     = acc[nb][2];
            dst[(row0 + 8) * HD + 1] = acc[nb][3];
        }
    }
}

// Fused edge kernel (tf32 tensor cores), unchanged from round 6.
__global__ void k_edge(const float* __restrict__ ea, const float* __restrict__ tdp,
                       const float* __restrict__ W1, const float* __restrict__ b1,
                       const float* __restrict__ W2, const float* __restrict__ b2,
                       const float* __restrict__ W3, const float* __restrict__ b3,
                       float* __restrict__ out) {
    __shared__ float As[64][33];
    __shared__ float Bs[32][132];
    __shared__ int   rs[64], cs[64];
    __shared__ float eas[64];
    __shared__ float w512s[256], bases[256];
    __shared__ float part[64][2];

    const int tid = threadIdx.x;
    const int m0 = blockIdx.x * 64;
    const float tdv = tdp[0];

    if (tid < 64) {
        int m = m0 + tid;
        if (m < NE) { rs[tid] = g_row[m]; cs[tid] = g_col[m]; eas[tid] = ea[m]; }
        else        { rs[tid] = 0;        cs[tid] = 0;        eas[tid] = 0.f;  }
    }
    for (int k = tid; k < 256; k += 256) {
        w512s[k] = W1[512 * HD + k];
        bases[k] = b1[k] + tdv * W1[513 * HD + k];
    }
    __syncthreads();

    const int lane = tid & 31;
    const int wid  = tid >> 5;
    const int mblk = wid >> 1;
    const int nhalf = wid & 1;
    float acc[8][4] = {};

    const int arow = tid >> 2;
    const int ak   = (tid & 3) << 3;
    const float* p1r = g_hB   + (size_t)rs[arow] * HD;
    const float* p2r = g_aggr + (size_t)cs[arow] * HD;
    const float eav = eas[arow];

    for (int kk = 0; kk < 256; kk += 32) {
#pragma unroll
        for (int p = 0; p < 4; p++) {
            int r = (tid >> 5) + p * 8;
            int c4 = lane * 4;
            float4 w = *(const float4*)(W2 + (kk + r) * 128 + c4);
            Bs[r][c4 + 0] = to_tf32(w.x);
            Bs[r][c4 + 1] = to_tf32(w.y);
            Bs[r][c4 + 2] = to_tf32(w.z);
            Bs[r][c4 + 3] = to_tf32(w.w);
        }
        {
            float4 u  = *(const float4*)(p1r + kk + ak);
            float4 v  = *(const float4*)(p2r + kk + ak);
            float4 u2 = *(const float4*)(p1r + kk + ak + 4);
            float4 v2 = *(const float4*)(p2r + kk + ak + 4);
            int kb = kk + ak;
            As[arow][ak + 0] = to_tf32(fmaxf(u.x  + v.x  + eav * w512s[kb + 0] + bases[kb + 0], 0.f));
            As[arow][ak + 1] = to_tf32(fmaxf(u.y  + v.y  + eav * w512s[kb + 1] + bases[kb + 1], 0.f));
            As[arow][ak + 2] = to_tf32(fmaxf(u.z  + v.z  + eav * w512s[kb + 2] + bases[kb + 2], 0.f));
            As[arow][ak + 3] = to_tf32(fmaxf(u.w  + v.w  + eav * w512s[kb + 3] + bases[kb + 3], 0.f));
            As[arow][ak + 4] = to_tf32(fmaxf(u2.x + v2.x + eav * w512s[kb + 4] + bases[kb + 4], 0.f));
            As[arow][ak + 5] = to_tf32(fmaxf(u2.y + v2.y + eav * w512s[kb + 5] + bases[kb + 5], 0.f));
            As[arow][ak + 6] = to_tf32(fmaxf(u2.z + v2.z + eav * w512s[kb + 6] + bases[kb + 6], 0.f));
            As[arow][ak + 7] = to_tf32(fmaxf(u2.w + v2.w + eav * w512s[kb + 7] + bases[kb + 7], 0.f));
        }
        __syncthreads();
#pragma unroll
        for (int ks = 0; ks < 4; ks++) {
            int kb = ks * 8;
            int r0 = mblk * 16 + (lane >> 2);
            uint32_t a0 = __float_as_uint(As[r0][kb + (lane & 3)]);
            uint32_t a1 = __float_as_uint(As[r0 + 8][kb + (lane & 3)]);
            uint32_t a2 = __float_as_uint(As[r0][kb + (lane & 3) + 4]);
            uint32_t a3 = __float_as_uint(As[r0 + 8][kb + (lane & 3) + 4]);
#pragma unroll
            for (int nb = 0; nb < 8; nb++) {
                int nc = nhalf * 64 + nb * 8 + (lane >> 2);
                uint32_t b0 = __float_as_uint(Bs[kb + (lane & 3)][nc]);
                uint32_t b1r = __float_as_uint(Bs[kb + (lane & 3) + 4][nc]);
                MMA_TF32(acc[nb], a0, a1, a2, a3, b0, b1r);
            }
        }
        __syncthreads();
    }

    float pr0 = 0.f, pr1 = 0.f;
#pragma unroll
    for (int nb = 0; nb < 8; nb++) {
        int ncol = nhalf * 64 + nb * 8 + 2 * (lane & 3);
        float w3a = W3[ncol], w3b = W3[ncol + 1];
        float b2a = b2[ncol], b2b = b2[ncol + 1];
        pr0 += fmaxf(acc[nb][0] + b2a, 0.f) * w3a + fmaxf(acc[nb][1] + b2b, 0.f) * w3b;
        pr1 += fmaxf(acc[nb][2] + b2a, 0.f) * w3a + fmaxf(acc[nb][3] + b2b, 0.f) * w3b;
    }
    pr0 += __shfl_xor_sync(0xffffffff, pr0, 1);
    pr0 += __shfl_xor_sync(0xffffffff, pr0, 2);
    pr1 += __shfl_xor_sync(0xffffffff, pr1, 1);
    pr1 += __shfl_xor_sync(0xffffffff, pr1, 2);
    if ((lane & 3) == 0) {
        part[mblk * 16 + (lane >> 2)][nhalf]     = pr0;
        part[mblk * 16 + (lane >> 2) + 8][nhalf] = pr1;
    }
    __syncthreads();
    if (tid < 64) {
        int m = m0 + tid;
        if (m < NE) out[m] = part[tid][0] + part[tid][1] + b3[0];
    }
}

// ---------------- host launcher ---------------------------------------------
extern "C" void kernel_launch(void* const* d_in, const int* in_sizes, int n_in,
                              void* d_out, int out_size) {
    const float* x   = (const float*)d_in[0];
    const void*  ei  = d_in[1];
    const float* ea  = (const float*)d_in[2];
    const float* td  = (const float*)d_in[3];
    const float* Wl1 = (const float*)d_in[4];
    const float* bl1 = (const float*)d_in[5];
    const float* Wr1 = (const float*)d_in[6];
    const float* Wl2 = (const float*)d_in[7];
    const float* bl2 = (const float*)d_in[8];
    const float* Wr2 = (const float*)d_in[9];
    const float* Wl3 = (const float*)d_in[10];
    const float* bl3 = (const float*)d_in[11];
    const float* Wr3 = (const float*)d_in[12];
    const float* W1  = (const float*)d_in[13];
    const float* b1  = (const float*)d_in[14];
    const float* W2  = (const float*)d_in[15];
    const float* b2  = (const float*)d_in[16];
    const float* W3  = (const float*)d_in[17];
    const float* b3  = (const float*)d_in[18];
    float* out = (float*)d_out;

    const int SMEM_TC = (2304 * 2 + 4224 * 2) * 4;  // 52224 B
    static int attr_done = 0;
    if (!attr_done) {
        cudaFuncSetAttribute(k_sage_tc, cudaFuncAttributeMaxDynamicSharedMemorySize, SMEM_TC);
        cudaFuncSetAttribute(k_proj_tc, cudaFuncAttributeMaxDynamicSharedMemorySize, SMEM_TC);
        attr_done = 1;
    }

    k_zero_small<<<160, 256>>>();
    k_detect<<<64, 256>>>((const int*)ei);
    k_idx_count<<<(NE + 255) / 256, 256>>>(ei);
    k_inv<<<(NN + 255) / 256, 256>>>();
    k_scatter3<<<(NE + 255) / 256, 256>>>(x);
    k_sage1<<<NN, 256>>>(x, Wl1, bl1, Wr1);           // -> g_hA

    dim3 gs_tc(HD / 128, (NN + 63) / 64);             // (2, 313)

    // layer 2: read g_hA -> write g_hB
    k_zero_aggr<<<2048, 256>>>();
    k_scatter<<<(NE * 64) / 256, 256>>>(0);
    k_sage_tc<<<gs_tc, 256, SMEM_TC>>>(0, Wl2, Wr2, bl2);

    // layer 3: read g_hB -> write g_hA
    k_zero_aggr<<<2048, 256>>>();
    k_scatter<<<(NE * 64) / 256, 256>>>(1);
    k_sage_tc<<<gs_tc, 256, SMEM_TC>>>(1, Wl3, Wr3, bl3);

    // fused projections: [P1|P2] -> g_hB | g_aggr
    dim3 gp_tc(4, (NN + 63) / 64);                    // N=512
    k_proj_tc<<<gp_tc, 256, SMEM_TC>>>(W1);

    // fused edge MLP (tf32 mma)
    k_edge<<<(NE + 63) / 64, 256>>>(ea, td, W1, b1, W2, b2, W3, b3, out);
}

// round 8
// speedup vs baseline: 4.3188x; 1.1037x over previous
#include <cuda_runtime.h>
#include <cstdint>

#define NN 20000
#define NE 300000
#define HD 256
#define MAXDEG 96

// ---------------- scratch (device globals; referenced ONLY in device code) --
__device__ int   g_cnt[NN];
__device__ __align__(16) float g_inv[NN];
__device__ __align__(16) float g_aggr3[NN * 4];
__device__ __align__(16) float g_aggr[NN * HD];   // aggr; later reused as P2
__device__ __align__(16) float g_hA[NN * HD];
__device__ __align__(16) float g_hB[NN * HD];     // layer2 h; later reused as P1
__device__ int g_row[NE];
__device__ int g_col[NE];
__device__ int g_elist[NN * MAXDEG];

__device__ __forceinline__ float to_tf32(float x) {
    uint32_t u;
    asm("cvt.rna.tf32.f32 %0, %1;" : "=r"(u) : "f"(x));
    return __uint_as_float(u);
}

#define MMA_TF32(acc, a0, a1, a2, a3, b0, b1)                                   \
    asm volatile(                                                               \
        "mma.sync.aligned.m16n8k8.row.col.f32.tf32.tf32.f32 "                   \
        "{%0,%1,%2,%3}, {%4,%5,%6,%7}, {%8,%9}, {%0,%1,%2,%3};"                 \
        : "+f"(acc[0]), "+f"(acc[1]), "+f"(acc[2]), "+f"(acc[3])                \
        : "r"(a0), "r"(a1), "r"(a2), "r"(a3), "r"(b0), "r"(b1))

// ---------------- preamble kernels ------------------------------------------
// launch 1: zero counters and x-aggregate
__global__ void k_init() {
    int i = blockIdx.x * blockDim.x + threadIdx.x;
    int stride = gridDim.x * blockDim.x;
    for (int j = i; j < NN; j += stride) g_cnt[j] = 0;
    for (int j = i; j < NN * 4; j += stride) g_aggr3[j] = 0.f;
}

// launch 2: decode indices (local dtype detection), fill edge list buckets,
// and scatter the 3-dim input features.
__global__ void k_idx_fill(const void* __restrict__ eiv, const float* __restrict__ x) {
    __shared__ int is64_s;
    const int tid = threadIdx.x;
    if (tid == 0) is64_s = 1;
    __syncthreads();
    // Fixed 256-word sample of high-words: int64 data (values in [0,2^31)) has
    // all-zero odd words; int32 data has random node ids there (P(all 0)~0).
    {
        const int* w = (const int*)eiv;
        if (w[2 * tid + 1] != 0) is64_s = 0;
    }
    __syncthreads();
    const int is64 = is64_s;

    int e = blockIdx.x * blockDim.x + tid;
    if (e < NE) {
        int r, c;
        if (is64) {
            const long long* ei = (const long long*)eiv;
            r = (int)ei[e];
            c = (int)ei[NE + e];
        } else {
            const int* ei = (const int*)eiv;
            r = ei[e];
            c = ei[NE + e];
        }
        r = min(max(r, 0), NN - 1);
        c = min(max(c, 0), NN - 1);
        g_row[e] = r;
        g_col[e] = c;
        int pos = atomicAdd(&g_cnt[c], 1);
        if (pos < MAXDEG) g_elist[c * MAXDEG + pos] = r;
        atomicAdd(&g_aggr3[4 * c + 0], x[3 * r + 0]);
        atomicAdd(&g_aggr3[4 * c + 1], x[3 * r + 1]);
        atomicAdd(&g_aggr3[4 * c + 2], x[3 * r + 2]);
    }
}

// launch 3: layer 1 (d_in=3) + per-node inv computation. Writes g_hA, g_inv.
__global__ void k_sage1(const float* __restrict__ x, const float* __restrict__ Wl,
                        const float* __restrict__ bl, const float* __restrict__ Wr) {
    int n = blockIdx.x;
    int j = threadIdx.x;
    __shared__ float a[3], xs[3], inv_s;
    if (j == 0) {
        float inv = 1.f / fmaxf((float)g_cnt[n], 1.f);
        g_inv[n] = inv;
        inv_s = inv;
    }
    __syncthreads();
    if (j < 3) {
        a[j]  = g_aggr3[4 * n + j] * inv_s;
        xs[j] = x[3 * n + j];
    }
    __syncthreads();
    float v = bl[j];
#pragma unroll
    for (int d = 0; d < 3; d++)
        v += a[d] * Wl[d * HD + j] + xs[d] * Wr[d * HD + j];
    g_hA[n * HD + j] = fmaxf(v, 0.f);
}

// Gather aggregation (atomic-free): aggr[n] = inv[n] * sum_{e: col=n} h[elist].
// Warp per node, lane owns 2 float4 columns. src: 0 -> g_hA, 1 -> g_hB.
__global__ void k_gather(int src) {
    const float4* h4 = (const float4*)(src ? g_hB : g_hA);
    const int lane = threadIdx.x & 31;
    const int node = blockIdx.x * 8 + (threadIdx.x >> 5);
    if (node >= NN) return;
    const int deg = min(g_cnt[node], MAXDEG);
    const float inv = g_inv[node];
    const int* el = g_elist + node * MAXDEG;
    float4 a0 = make_float4(0.f, 0.f, 0.f, 0.f);
    float4 a1 = make_float4(0.f, 0.f, 0.f, 0.f);
    for (int j = 0; j < deg; j++) {
        int s = el[j];
        float4 v0 = h4[(size_t)s * 64 + lane];
        float4 v1 = h4[(size_t)s * 64 + 32 + lane];
        a0.x += v0.x; a0.y += v0.y; a0.z += v0.z; a0.w += v0.w;
        a1.x += v1.x; a1.y += v1.y; a1.z += v1.z; a1.w += v1.w;
    }
    a0.x *= inv; a0.y *= inv; a0.z *= inv; a0.w *= inv;
    a1.x *= inv; a1.y *= inv; a1.z *= inv; a1.w *= inv;
    float4* o4 = (float4*)g_aggr;
    o4[(size_t)node * 64 + lane]      = a0;
    o4[(size_t)node * 64 + 32 + lane] = a1;
}

// ---------------------------------------------------------------------------
// Tensor-core SAGE layer (3xTF32 split precision, fp32-quality):
//   hout = relu( aggr @ Wl + hprev @ Wr + bl )   (aggr pre-scaled by inv)
// M=NN, N=256, virtual K=512. Tile 64x128, 8 warps, BK=32.
// ---------------------------------------------------------------------------
__global__ void k_sage_tc(int src, const float* __restrict__ Wl,
                          const float* __restrict__ Wr, const float* __restrict__ bl) {
    const float* hprev = src ? g_hB : g_hA;
    float*       hout  = src ? g_hA : g_hB;
    extern __shared__ float sm[];
    float* Ah = sm;                 // 64*36
    float* Al = sm + 2304;
    float* Bh = sm + 4608;          // 32*132
    float* Bl = sm + 8832;

    const int tid = threadIdx.x;
    const int m0 = blockIdx.y * 64;
    const int n0 = blockIdx.x * 128;
    const int lane = tid & 31, wid = tid >> 5;
    const int mblk = wid >> 1, nhalf = wid & 1;
    const int g = lane >> 2, t = lane & 3;
    const int arow = tid >> 2, ak = (tid & 3) << 3;
    const int mA = m0 + arow;
    const bool mok = (mA < NN);
    const float* aggp = g_aggr + (size_t)mA * HD;
    const float* hpp  = hprev  + (size_t)mA * HD;
    float acc[8][4] = {};

    for (int kk = 0; kk < 512; kk += 32) {
        {
            float v[8];
            if (mok) {
                const float* p = (kk < 256) ? (aggp + kk + ak) : (hpp + (kk - 256) + ak);
                float4 u  = *(const float4*)p;
                float4 u2 = *(const float4*)(p + 4);
                v[0] = u.x;  v[1] = u.y;  v[2] = u.z;  v[3] = u.w;
                v[4] = u2.x; v[5] = u2.y; v[6] = u2.z; v[7] = u2.w;
            } else {
#pragma unroll
                for (int i = 0; i < 8; i++) v[i] = 0.f;
            }
#pragma unroll
            for (int i = 0; i < 8; i++) {
                float hi = to_tf32(v[i]);
                Ah[arow * 36 + ak + i] = hi;
                Al[arow * 36 + ak + i] = to_tf32(v[i] - hi);
            }
        }
        {
            const float* W = (kk < 256) ? Wl : Wr;
            int kbase = kk & 255;
#pragma unroll
            for (int p = 0; p < 4; p++) {
                int r = wid + p * 8;
                int c = lane * 4;
                float4 w = *(const float4*)(W + (kbase + r) * HD + n0 + c);
                float h0 = to_tf32(w.x), h1 = to_tf32(w.y), h2 = to_tf32(w.z), h3 = to_tf32(w.w);
                Bh[r * 132 + c + 0] = h0; Bl[r * 132 + c + 0] = to_tf32(w.x - h0);
                Bh[r * 132 + c + 1] = h1; Bl[r * 132 + c + 1] = to_tf32(w.y - h1);
                Bh[r * 132 + c + 2] = h2; Bl[r * 132 + c + 2] = to_tf32(w.z - h2);
                Bh[r * 132 + c + 3] = h3; Bl[r * 132 + c + 3] = to_tf32(w.w - h3);
            }
        }
        __syncthreads();
#pragma unroll
        for (int ks = 0; ks < 4; ks++) {
            int kb = ks * 8;
            int r0 = mblk * 16 + g;
            uint32_t ah0 = __float_as_uint(Ah[r0 * 36 + kb + t]);
            uint32_t ah1 = __float_as_uint(Ah[(r0 + 8) * 36 + kb + t]);
            uint32_t ah2 = __float_as_uint(Ah[r0 * 36 + kb + t + 4]);
            uint32_t ah3 = __float_as_uint(Ah[(r0 + 8) * 36 + kb + t + 4]);
            uint32_t al0 = __float_as_uint(Al[r0 * 36 + kb + t]);
            uint32_t al1 = __float_as_uint(Al[(r0 + 8) * 36 + kb + t]);
            uint32_t al2 = __float_as_uint(Al[r0 * 36 + kb + t + 4]);
            uint32_t al3 = __float_as_uint(Al[(r0 + 8) * 36 + kb + t + 4]);
#pragma unroll
            for (int nb = 0; nb < 8; nb++) {
                int nc = nhalf * 64 + nb * 8 + g;
                uint32_t bh0 = __float_as_uint(Bh[(kb + t) * 132 + nc]);
                uint32_t bh1 = __float_as_uint(Bh[(kb + t + 4) * 132 + nc]);
                uint32_t bl0 = __float_as_uint(Bl[(kb + t) * 132 + nc]);
                uint32_t bl1 = __float_as_uint(Bl[(kb + t + 4) * 132 + nc]);
                MMA_TF32(acc[nb], ah0, ah1, ah2, ah3, bh0, bh1);
                MMA_TF32(acc[nb], ah0, ah1, ah2, ah3, bl0, bl1);
                MMA_TF32(acc[nb], al0, al1, al2, al3, bh0, bh1);
            }
        }
        __syncthreads();
    }
    int row0 = m0 + mblk * 16 + g;
#pragma unroll
    for (int nb = 0; nb < 8; nb++) {
        int col = n0 + nhalf * 64 + nb * 8 + 2 * t;
        float bla = bl[col], blb = bl[col + 1];
        if (row0 < NN) {
            hout[row0 * HD + col]     = fmaxf(acc[nb][0] + bla, 0.f);
            hout[row0 * HD + col + 1] = fmaxf(acc[nb][1] + blb, 0.f);
        }
        if (row0 + 8 < NN) {
            hout[(row0 + 8) * HD + col]     = fmaxf(acc[nb][2] + bla, 0.f);
            hout[(row0 + 8) * HD + col + 1] = fmaxf(acc[nb][3] + blb, 0.f);
        }
    }
}

// ---------------------------------------------------------------------------
// Fused projection GEMM (3xTF32): [P1 | P2] = g_hA @ [W1a | W1b]
// ---------------------------------------------------------------------------
__global__ void k_proj_tc(const float* __restrict__ W1) {
    extern __shared__ float sm[];
    float* Ah = sm;
    float* Al = sm + 2304;
    float* Bh = sm + 4608;
    float* Bl = sm + 8832;

    const int tid = threadIdx.x;
    const int m0 = blockIdx.y * 64;
    const int n0 = blockIdx.x * 128;
    const int lane = tid & 31, wid = tid >> 5;
    const int mblk = wid >> 1, nhalf = wid & 1;
    const int g = lane >> 2, t = lane & 3;
    const int arow = tid >> 2, ak = (tid & 3) << 3;
    const int mA = m0 + arow;
    const bool mok = (mA < NN);
    const float* hp = g_hA + (size_t)mA * HD;
    float acc[8][4] = {};

    for (int kk = 0; kk < 256; kk += 32) {
        {
            float v[8];
            if (mok) {
                float4 u  = *(const float4*)(hp + kk + ak);
                float4 u2 = *(const float4*)(hp + kk + ak + 4);
                v[0] = u.x;  v[1] = u.y;  v[2] = u.z;  v[3] = u.w;
                v[4] = u2.x; v[5] = u2.y; v[6] = u2.z; v[7] = u2.w;
            } else {
#pragma unroll
                for (int i = 0; i < 8; i++) v[i] = 0.f;
            }
#pragma unroll
            for (int i = 0; i < 8; i++) {
                float hi = to_tf32(v[i]);
                Ah[arow * 36 + ak + i] = hi;
                Al[arow * 36 + ak + i] = to_tf32(v[i] - hi);
            }
        }
        {
#pragma unroll
            for (int p = 0; p < 4; p++) {
                int r = wid + p * 8;
                int c = lane * 4;
                int n = n0 + c;
                int rowoff = (n >= 256) ? 256 : 0;
                float4 w = *(const float4*)(W1 + (size_t)(kk + r + rowoff) * HD + (n & 255));
                float h0 = to_tf32(w.x), h1 = to_tf32(w.y), h2 = to_tf32(w.z), h3 = to_tf32(w.w);
                Bh[r * 132 + c + 0] = h0; Bl[r * 132 + c + 0] = to_tf32(w.x - h0);
                Bh[r * 132 + c + 1] = h1; Bl[r * 132 + c + 1] = to_tf32(w.y - h1);
                Bh[r * 132 + c + 2] = h2; Bl[r * 132 + c + 2] = to_tf32(w.z - h2);
                Bh[r * 132 + c + 3] = h3; Bl[r * 132 + c + 3] = to_tf32(w.w - h3);
            }
        }
        __syncthreads();
#pragma unroll
        for (int ks = 0; ks < 4; ks++) {
            int kb = ks * 8;
            int r0 = mblk * 16 + g;
            uint32_t ah0 = __float_as_uint(Ah[r0 * 36 + kb + t]);
            uint32_t ah1 = __float_as_uint(Ah[(r0 + 8) * 36 + kb + t]);
            uint32_t ah2 = __float_as_uint(Ah[r0 * 36 + kb + t + 4]);
            uint32_t ah3 = __float_as_uint(Ah[(r0 + 8) * 36 + kb + t + 4]);
            uint32_t al0 = __float_as_uint(Al[r0 * 36 + kb + t]);
            uint32_t al1 = __float_as_uint(Al[(r0 + 8) * 36 + kb + t]);
            uint32_t al2 = __float_as_uint(Al[r0 * 36 + kb + t + 4]);
            uint32_t al3 = __float_as_uint(Al[(r0 + 8) * 36 + kb + t + 4]);
#pragma unroll
            for (int nb = 0; nb < 8; nb++) {
                int nc = nhalf * 64 + nb * 8 + g;
                uint32_t bh0 = __float_as_uint(Bh[(kb + t) * 132 + nc]);
                uint32_t bh1 = __float_as_uint(Bh[(kb + t + 4) * 132 + nc]);
                uint32_t bl0 = __float_as_uint(Bl[(kb + t) * 132 + nc]);
                uint32_t bl1 = __float_as_uint(Bl[(kb + t + 4) * 132 + nc]);
                MMA_TF32(acc[nb], ah0, ah1, ah2, ah3, bh0, bh1);
                MMA_TF32(acc[nb], ah0, ah1, ah2, ah3, bl0, bl1);
                MMA_TF32(acc[nb], al0, al1, al2, al3, bh0, bh1);
            }
        }
        __syncthreads();
    }
    int row0 = m0 + mblk * 16 + g;
#pragma unroll
    for (int nb = 0; nb < 8; nb++) {
        int col = n0 + nhalf * 64 + nb * 8 + 2 * t;
        float* dst = (col < 256) ? (g_hB + col) : (g_aggr + col - 256);
        if (row0 < NN) {
            dst[row0 * HD]     = acc[nb][0];
            dst[row0 * HD + 1] = acc[nb][1];
        }
        if (row0 + 8 < NN) {
            dst[(row0 + 8) * HD]     = acc[nb][2];
            dst[(row0 + 8) * HD + 1] = acc[nb][3];
        }
    }
}

// Fused edge kernel (tf32 tensor cores), unchanged.
__global__ void k_edge(const float* __restrict__ ea, const float* __restrict__ tdp,
                       const float* __restrict__ W1, const float* __restrict__ b1,
                       const float* __restrict__ W2, const float* __restrict__ b2,
                       const float* __restrict__ W3, const float* __restrict__ b3,
                       float* __restrict__ out) {
    __shared__ float As[64][33];
    __shared__ float Bs[32][132];
    __shared__ int   rs[64], cs[64];
    __shared__ float eas[64];
    __shared__ float w512s[256], bases[256];
    __shared__ float part[64][2];

    const int tid = threadIdx.x;
    const int m0 = blockIdx.x * 64;
    const float tdv = tdp[0];

    if (tid < 64) {
        int m = m0 + tid;
        if (m < NE) { rs[tid] = g_row[m]; cs[tid] = g_col[m]; eas[tid] = ea[m]; }
        else        { rs[tid] = 0;        cs[tid] = 0;        eas[tid] = 0.f;  }
    }
    for (int k = tid; k < 256; k += 256) {
        w512s[k] = W1[512 * HD + k];
        bases[k] = b1[k] + tdv * W1[513 * HD + k];
    }
    __syncthreads();

    const int lane = tid & 31;
    const int wid  = tid >> 5;
    const int mblk = wid >> 1;
    const int nhalf = wid & 1;
    float acc[8][4] = {};

    const int arow = tid >> 2;
    const int ak   = (tid & 3) << 3;
    const float* p1r = g_hB   + (size_t)rs[arow] * HD;
    const float* p2r = g_aggr + (size_t)cs[arow] * HD;
    const float eav = eas[arow];

    for (int kk = 0; kk < 256; kk += 32) {
#pragma unroll
        for (int p = 0; p < 4; p++) {
            int r = (tid >> 5) + p * 8;
            int c4 = lane * 4;
            float4 w = *(const float4*)(W2 + (kk + r) * 128 + c4);
            Bs[r][c4 + 0] = to_tf32(w.x);
            Bs[r][c4 + 1] = to_tf32(w.y);
            Bs[r][c4 + 2] = to_tf32(w.z);
            Bs[r][c4 + 3] = to_tf32(w.w);
        }
        {
            float4 u  = *(const float4*)(p1r + kk + ak);
            float4 v  = *(const float4*)(p2r + kk + ak);
            float4 u2 = *(const float4*)(p1r + kk + ak + 4);
            float4 v2 = *(const float4*)(p2r + kk + ak + 4);
            int kb = kk + ak;
            As[arow][ak + 0] = to_tf32(fmaxf(u.x  + v.x  + eav * w512s[kb + 0] + bases[kb + 0], 0.f));
            As[arow][ak + 1] = to_tf32(fmaxf(u.y  + v.y  + eav * w512s[kb + 1] + bases[kb + 1], 0.f));
            As[arow][ak + 2] = to_tf32(fmaxf(u.z  + v.z  + eav * w512s[kb + 2] + bases[kb + 2], 0.f));
            As[arow][ak + 3] = to_tf32(fmaxf(u.w  + v.w  + eav * w512s[kb + 3] + bases[kb + 3], 0.f));
            As[arow][ak + 4] = to_tf32(fmaxf(u2.x + v2.x + eav * w512s[kb + 4] + bases[kb + 4], 0.f));
            As[arow][ak + 5] = to_tf32(fmaxf(u2.y + v2.y + eav * w512s[kb + 5] + bases[kb + 5], 0.f));
            As[arow][ak + 6] = to_tf32(fmaxf(u2.z + v2.z + eav * w512s[kb + 6] + bases[kb + 6], 0.f));
            As[arow][ak + 7] = to_tf32(fmaxf(u2.w + v2.w + eav * w512s[kb + 7] + bases[kb + 7], 0.f));
        }
        __syncthreads();
#pragma unroll
        for (int ks = 0; ks < 4; ks++) {
            int kb = ks * 8;
            int r0 = mblk * 16 + (lane >> 2);
            uint32_t a0 = __float_as_uint(As[r0][kb + (lane & 3)]);
            uint32_t a1 = __float_as_uint(As[r0 + 8][kb + (lane & 3)]);
            uint32_t a2 = __float_as_uint(As[r0][kb + (lane & 3) + 4]);
            uint32_t a3 = __float_as_uint(As[r0 + 8][kb + (lane & 3) + 4]);
#pragma unroll
            for (int nb = 0; nb < 8; nb++) {
                int nc = nhalf * 64 + nb * 8 + (lane >> 2);
                uint32_t b0 = __float_as_uint(Bs[kb + (lane & 3)][nc]);
                uint32_t b1r = __float_as_uint(Bs[kb + (lane & 3) + 4][nc]);
                MMA_TF32(acc[nb], a0, a1, a2, a3, b0, b1r);
            }
        }
        __syncthreads();
    }

    float pr0 = 0.f, pr1 = 0.f;
#pragma unroll
    for (int nb = 0; nb < 8; nb++) {
        int ncol = nhalf * 64 + nb * 8 + 2 * (lane & 3);
        float w3a = W3[ncol], w3b = W3[ncol + 1];
        float b2a = b2[ncol], b2b = b2[ncol + 1];
        pr0 += fmaxf(acc[nb][0] + b2a, 0.f) * w3a + fmaxf(acc[nb][1] + b2b, 0.f) * w3b;
        pr1 += fmaxf(acc[nb][2] + b2a, 0.f) * w3a + fmaxf(acc[nb][3] + b2b, 0.f) * w3b;
    }
    pr0 += __shfl_xor_sync(0xffffffff, pr0, 1);
    pr0 += __shfl_xor_sync(0xffffffff, pr0, 2);
    pr1 += __shfl_xor_sync(0xffffffff, pr1, 1);
    pr1 += __shfl_xor_sync(0xffffffff, pr1, 2);
    if ((lane & 3) == 0) {
        part[mblk * 16 + (lane >> 2)][nhalf]     = pr0;
        part[mblk * 16 + (lane >> 2) + 8][nhalf] = pr1;
    }
    __syncthreads();
    if (tid < 64) {
        int m = m0 + tid;
        if (m < NE) out[m] = part[tid][0] + part[tid][1] + b3[0];
    }
}

// ---------------- host launcher ---------------------------------------------
extern "C" void kernel_launch(void* const* d_in, const int* in_sizes, int n_in,
                              void* d_out, int out_size) {
    const float* x   = (const float*)d_in[0];
    const void*  ei  = d_in[1];
    const float* ea  = (const float*)d_in[2];
    const float* td  = (const float*)d_in[3];
    const float* Wl1 = (const float*)d_in[4];
    const float* bl1 = (const float*)d_in[5];
    const float* Wr1 = (const float*)d_in[6];
    const float* Wl2 = (const float*)d_in[7];
    const float* bl2 = (const float*)d_in[8];
    const float* Wr2 = (const float*)d_in[9];
    const float* Wl3 = (const float*)d_in[10];
    const float* bl3 = (const float*)d_in[11];
    const float* Wr3 = (const float*)d_in[12];
    const float* W1  = (const float*)d_in[13];
    const float* b1  = (const float*)d_in[14];
    const float* W2  = (const float*)d_in[15];
    const float* b2  = (const float*)d_in[16];
    const float* W3  = (const float*)d_in[17];
    const float* b3  = (const float*)d_in[18];
    float* out = (float*)d_out;

    const int SMEM_TC = (2304 * 2 + 4224 * 2) * 4;  // 52224 B
    static int attr_done = 0;
    if (!attr_done) {
        cudaFuncSetAttribute(k_sage_tc, cudaFuncAttributeMaxDynamicSharedMemorySize, SMEM_TC);
        cudaFuncSetAttribute(k_proj_tc, cudaFuncAttributeMaxDynamicSharedMemorySize, SMEM_TC);
        attr_done = 1;
    }

    // 1-3: preamble
    k_init<<<160, 256>>>();
    k_idx_fill<<<(NE + 255) / 256, 256>>>(ei, x);
    k_sage1<<<NN, 256>>>(x, Wl1, bl1, Wr1);            // -> g_hA, g_inv

    dim3 gs_tc(HD / 128, (NN + 63) / 64);              // (2, 313)

    // 4-5: layer 2 (gather from g_hA -> aggr, gemm -> g_hB)
    k_gather<<<(NN + 7) / 8, 256>>>(0);
    k_sage_tc<<<gs_tc, 256, SMEM_TC>>>(0, Wl2, Wr2, bl2);

    // 6-7: layer 3 (gather from g_hB -> aggr, gemm -> g_hA)
    k_gather<<<(NN + 7) / 8, 256>>>(1);
    k_sage_tc<<<gs_tc, 256, SMEM_TC>>>(1, Wl3, Wr3, bl3);

    // 8: fused projections: [P1|P2] -> g_hB | g_aggr
    dim3 gp_tc(4, (NN + 63) / 64);
    k_proj_tc<<<gp_tc, 256, SMEM_TC>>>(W1);

    // 9: fused edge MLP (tf32 mma)
    k_edge<<<(NE + 63) / 64, 256>>>(ea, td, W1, b1, W2, b2, W3, b3, out);
}